// round 9
// baseline (speedup 1.0000x reference)
#include <cuda_runtime.h>
#include <math.h>

#define N_    2
#define L_    512
#define H_    24
#define QK_   16
#define V_    16
#define HID_  128
#define CH_   504
#define EPS_  1e-6f
#define KPAD  20

// ---------------- scratch ----------------
__device__ float  g_q [N_*L_*H_*QK_];   // [n*L+i][h*16+d]
__device__ float  g_kT[N_*H_*QK_*L_];   // [n][h][d][j]
__device__ float  g_vT[N_*H_*V_ *L_];   // [n][h][d][j]
__device__ float  g_a [N_*H_*L_*3];
__device__ float  g_b [N_*H_*L_*3];
__device__ float  g_cc[N_*L_*CH_];
__device__ float4 g_u [N_*L_*L_];       // (R_i^T t_j, |R_i^T t_j|^2)  8MB
__device__ float  g_st[(size_t)N_*H_*L_*L_]; // c1*q.k + bias            50MB

__device__ __forceinline__ float rsqrt_fast(float x) {
    float r; asm("rsqrt.approx.f32 %0,%1;" : "=f"(r) : "f"(x)); return r;
}
__device__ __forceinline__ float ex2_fast(float x) {
    float r; asm("ex2.approx.f32 %0,%1;" : "=f"(r) : "f"(x)); return r;
}
// fast acos with built-in clamp: A&S 4.4.45, |err| <= 6.8e-5 (budget 1e-3)
__device__ __forceinline__ float acos_fast(float x) {
    float ax = fminf(fabsf(x), 1.0f);
    float s; asm("sqrt.approx.f32 %0,%1;" : "=f"(s) : "f"(1.0f - ax));
    float p = fmaf(ax, -0.0187293f, 0.0742610f);
    p = fmaf(ax, p, -0.2121144f);
    p = fmaf(ax, p, 1.5707288f);
    float r = s * p;
    return x < 0.f ? 3.14159265359f - r : r;
}

// ================= kernel A: fused projections (proven ~22us) =================
#define PJS 68

__global__ void __launch_bounds__(256) proj_kernel(
    const float* __restrict__ x,
    const float* __restrict__ Wq, const float* __restrict__ Wk,
    const float* __restrict__ Wv, const float* __restrict__ bv,
    const float* __restrict__ Wa, const float* __restrict__ ba,
    const float* __restrict__ Wb, const float* __restrict__ bb)
{
    __shared__ float xs[32*PJS];
    __shared__ float ws[32*PJS];

    const int tid = threadIdx.x;
    const int rt  = blockIdx.x;
    const int ct  = blockIdx.y;

    const int tx = tid & 15;
    const int ty = tid >> 4;

    float acc[4][4];
    #pragma unroll
    for (int r = 0; r < 4; r++)
        #pragma unroll
        for (int c = 0; c < 4; c++) acc[r][c] = 0.f;

    #pragma unroll 1
    for (int chunk = 0; chunk < 4; chunk++) {
        __syncthreads();
        #pragma unroll
        for (int it = 0; it < 2; it++) {
            const int idx = it*256 + tid;
            const int kq = idx & 7;
            const int m  = idx >> 3;
            const float4 v = *(const float4*)(x + (size_t)(rt*64 + m)*HID_ + chunk*32 + kq*4);
            xs[(kq*4+0)*PJS + m] = v.x;
            xs[(kq*4+1)*PJS + m] = v.y;
            xs[(kq*4+2)*PJS + m] = v.z;
            xs[(kq*4+3)*PJS + m] = v.w;
        }
        #pragma unroll
        for (int it = 0; it < 2; it++) {
            const int idx = it*256 + tid;
            const int kq = idx & 7;
            const int cl = idx >> 3;
            const int c  = min(ct*64 + cl, 1295);
            const float* wrow;
            if      (c <  384) wrow = Wq + (size_t)c*HID_;
            else if (c <  768) wrow = Wk + (size_t)(c- 384)*HID_;
            else if (c < 1152) wrow = Wv + (size_t)(c- 768)*HID_;
            else if (c < 1224) wrow = Wa + (size_t)(c-1152)*HID_;
            else               wrow = Wb + (size_t)(c-1224)*HID_;
            const float4 v = *(const float4*)(wrow + chunk*32 + kq*4);
            ws[(kq*4+0)*PJS + cl] = v.x;
            ws[(kq*4+1)*PJS + cl] = v.y;
            ws[(kq*4+2)*PJS + cl] = v.z;
            ws[(kq*4+3)*PJS + cl] = v.w;
        }
        __syncthreads();

        #pragma unroll
        for (int k = 0; k < 32; k++) {
            const float4 xv = *(const float4*)(xs + k*PJS + tx*4);
            const float4 wv = *(const float4*)(ws + k*PJS + ty*4);
            const float xa[4] = {xv.x, xv.y, xv.z, xv.w};
            const float wa[4] = {wv.x, wv.y, wv.z, wv.w};
            #pragma unroll
            for (int r = 0; r < 4; r++)
                #pragma unroll
                for (int c = 0; c < 4; c++)
                    acc[r][c] = fmaf(xa[r], wa[c], acc[r][c]);
        }
    }

    #pragma unroll
    for (int r = 0; r < 4; r++) {
        const int gi = rt*64 + tx*4 + r;
        const int n = gi >> 9, i = gi & 511;
        #pragma unroll
        for (int cv = 0; cv < 4; cv++) {
            const int c = ct*64 + ty*4 + cv;
            if (c >= 1296) continue;
            float val = acc[r][cv];
            if (c < 384) {
                g_q[(size_t)gi*384 + c] = val;
            } else if (c < 768) {
                int cc = c - 384; int h = cc >> 4, d = cc & 15;
                g_kT[((size_t)(n*H_ + h)*QK_ + d)*L_ + i] = val;
            } else if (c < 1152) {
                int cc = c - 768; int h = cc >> 4, d = cc & 15;
                g_vT[((size_t)(n*H_ + h)*V_ + d)*L_ + i] = val + bv[cc];
            } else if (c < 1224) {
                int cc = c - 1152; int h = cc/3, xx = cc - h*3;
                g_a[((size_t)(n*H_ + h)*L_ + i)*3 + xx] = val + ba[cc];
            } else {
                int cc = c - 1224; int h = cc/3, xx = cc - h*3;
                g_b[((size_t)(n*H_ + h)*L_ + i)*3 + xx] = val + bb[cc];
            }
        }
    }
}

// ================= kernel U: u[n][i][j] = (R_i^T t_j, |.|^2) =================
__global__ void __launch_bounds__(256) u_kernel(
    const float* __restrict__ Rm, const float* __restrict__ t)
{
    __shared__ float4 ts4[L_];
    const int tid = threadIdx.x;
    const int n = blockIdx.y;
    const int i = blockIdx.x*8 + (tid >> 5);
    const int lane = tid & 31;

    for (int j = tid; j < L_; j += 256) {
        const float* tp = t + (size_t)(n*L_ + j)*3;
        ts4[j] = make_float4(tp[0], tp[1], tp[2], 0.f);
    }
    __syncthreads();

    const float* Rp = Rm + (size_t)(n*L_ + i)*9;
    const float R00=Rp[0],R01=Rp[1],R02=Rp[2],
                R10=Rp[3],R11=Rp[4],R12=Rp[5],
                R20=Rp[6],R21=Rp[7],R22=Rp[8];

    float4* up = g_u + (size_t)(n*L_ + i)*L_;
    #pragma unroll 2
    for (int it = 0; it < 16; it++) {
        const int j = it*32 + lane;
        const float4 tj = ts4[j];
        const float ux = R00*tj.x + R10*tj.y + R20*tj.z;
        const float uy = R01*tj.x + R11*tj.y + R21*tj.z;
        const float uz = R02*tj.x + R12*tj.y + R22*tj.z;
        const float uw = fmaf(ux,ux, fmaf(uy,uy, uz*uz));
        up[j] = make_float4(ux, uy, uz, uw);
    }
}

// ================= kernel S: st = c1*(q.k) + bias  (batched GEMM) =================
__global__ void __launch_bounds__(256) st_kernel()
{
    __shared__ float qs[16*68];   // [d][i_local]
    __shared__ float ksm[16*64];  // [d][j_local]

    const int tid = threadIdx.x;
    const int i0 = blockIdx.x * 64;
    const int j0 = blockIdx.y * 64;
    const int nh = blockIdx.z;            // n*H + h
    const int n = nh / H_, h = nh - n*H_;

    {   // q tile: 64 rows x 16 d
        const int il = tid >> 2, dq = tid & 3;
        const float4 v = *(const float4*)(g_q + (size_t)(n*L_ + i0 + il)*384 + h*16 + dq*4);
        qs[(dq*4+0)*68 + il] = v.x;
        qs[(dq*4+1)*68 + il] = v.y;
        qs[(dq*4+2)*68 + il] = v.z;
        qs[(dq*4+3)*68 + il] = v.w;
    }
    {   // k tile: 16 d x 64 j
        const int dk = tid >> 4, j4 = tid & 15;
        const float4 v = *(const float4*)(g_kT + ((size_t)nh*16 + dk)*L_ + j0 + j4*4);
        *(float4*)(ksm + dk*64 + j4*4) = v;
    }
    __syncthreads();

    const int tx = tid & 15;   // j group (4 cols)
    const int ty = tid >> 4;   // i group (4 rows)

    float acc[4][4];
    #pragma unroll
    for (int r = 0; r < 4; r++)
        #pragma unroll
        for (int c = 0; c < 4; c++) acc[r][c] = 0.f;

    #pragma unroll
    for (int d = 0; d < 16; d++) {
        const float4 qv = *(const float4*)(qs + d*68 + ty*4);
        const float4 kv = *(const float4*)(ksm + d*64 + tx*4);
        const float qa[4] = {qv.x, qv.y, qv.z, qv.w};
        const float ka[4] = {kv.x, kv.y, kv.z, kv.w};
        #pragma unroll
        for (int r = 0; r < 4; r++)
            #pragma unroll
            for (int c = 0; c < 4; c++)
                acc[r][c] = fmaf(qa[r], ka[c], acc[r][c]);
    }

    const float C1 = 0.70710678118f * 0.25f * 1.44269504089f;
    const float BIAS = -4.0f * 1.44269504089f;
    #pragma unroll
    for (int r = 0; r < 4; r++) {
        const int i = i0 + ty*4 + r;
        float4 o;
        o.x = fmaf(C1, acc[r][0], BIAS);
        o.y = fmaf(C1, acc[r][1], BIAS);
        o.z = fmaf(C1, acc[r][2], BIAS);
        o.w = fmaf(C1, acc[r][3], BIAS);
        *(float4*)(g_st + ((size_t)nh*L_ + i)*L_ + j0 + tx*4) = o;
    }
}

// ================= kernel B: ray attention (hoisted geometry) =================
// r = u_j - c_i ;  rr = |u|^2 - 2 u.c + |c|^2 ;  r.a' = u.a' - c.a'
// sum(p r) = sum(p u) - s*c  -> fixed after the loop.
__device__ __forceinline__ void attn_reduce_store(
    float av[16], float s, float pu0, float pu1, float pu2, float pth,
    int lane, float* __restrict__ cc, int h, float c0, float c1, float c2)
{
    #pragma unroll
    for (int k = 0; k < 4; k++) {
        const int half = 8 >> k;
        const bool up = (lane >> k) & 1;
        #pragma unroll
        for (int t = 0; t < half; t++) {
            float send = up ? av[t] : av[t + half];
            float recv = __shfl_xor_sync(0xffffffffu, send, 1 << k);
            av[t] = (up ? av[t + half] : av[t]) + recv;
        }
    }
    av[0] += __shfl_xor_sync(0xffffffffu, av[0], 16);

    #pragma unroll
    for (int off = 16; off > 0; off >>= 1) {
        s   += __shfl_xor_sync(0xffffffffu, s,   off);
        pu0 += __shfl_xor_sync(0xffffffffu, pu0, off);
        pu1 += __shfl_xor_sync(0xffffffffu, pu1, off);
        pu2 += __shfl_xor_sync(0xffffffffu, pu2, off);
        pth += __shfl_xor_sync(0xffffffffu, pth, off);
    }
    const float inv = 1.0f / s;
    if (lane < 16) {
        const int d = (int)(__brev((unsigned)lane) >> 28);
        cc[h*16 + d] = av[0] * inv;
    }
    if (lane == 0) {
        const float ra0 = pu0*inv - c0;
        const float ra1 = pu1*inv - c1;
        const float ra2 = pu2*inv - c2;
        cc[384 + h*3 + 0] = ra0;
        cc[384 + h*3 + 1] = ra1;
        cc[384 + h*3 + 2] = ra2;
        cc[456 + h] = sqrtf(ra0*ra0 + ra1*ra1 + ra2*ra2);
        cc[480 + h] = pth*inv;
    }
}

__global__ void __launch_bounds__(256, 2) attn_kernel(
    const float* __restrict__ alpha, const float* __restrict__ beta)
{
    __shared__ float vs[L_*KPAD];   // [j][20]  40KB

    const int tid = threadIdx.x;
    const int n = blockIdx.z, h = blockIdx.y;
    const int i0 = blockIdx.x * 64;

    const float* vb = g_vT + (size_t)(n*H_ + h)*V_*L_;
    for (int idx = tid; idx < QK_*L_; idx += 256) {
        int d = idx >> 9, j = idx & 511;
        vs[j*KPAD + d] = vb[idx];
    }
    __syncthreads();

    const float LOG2E = 1.44269504089f;
    const float al = log1pf(expf(alpha[h])) * 0.70710678118f * LOG2E;
    const float be = log1pf(expf(beta[h]))  * 0.70710678118f * LOG2E;
    const int warp = tid >> 5, lane = tid & 31;

    #pragma unroll 1
    for (int pass = 0; pass < 4; pass++) {
        const int iA = i0 + warp*8 + pass*2;
        const int iB = iA + 1;

        // ---- per-row constants ----
        float cA0,cA1,cA2, mA0,mA1,mA2, cwA, aA0,aA1,aA2, caA;
        float cB0,cB1,cB2, mB0,mB1,mB2, cwB, aB0,aB1,aB2, caB;
        {
            const float4 uii = g_u[((size_t)(n*L_ + iA))*L_ + iA];
            const float* bp_ = g_b + ((size_t)(n*H_ + h)*L_ + iA)*3;
            cA0 = uii.x + bp_[0]; cA1 = uii.y + bp_[1]; cA2 = uii.z + bp_[2];
            mA0 = -2.f*cA0; mA1 = -2.f*cA1; mA2 = -2.f*cA2;
            cwA = fmaf(cA0,cA0, fmaf(cA1,cA1, cA2*cA2));
            const float* ap = g_a + ((size_t)(n*H_ + h)*L_ + iA)*3;
            float a0=ap[0], a1=ap[1], a2=ap[2];
            const float inv = 1.0f/(sqrtf(a0*a0+a1*a1+a2*a2) + EPS_);
            aA0=a0*inv; aA1=a1*inv; aA2=a2*inv;
            caA = fmaf(cA0,aA0, fmaf(cA1,aA1, cA2*aA2));
        }
        {
            const float4 uii = g_u[((size_t)(n*L_ + iB))*L_ + iB];
            const float* bp_ = g_b + ((size_t)(n*H_ + h)*L_ + iB)*3;
            cB0 = uii.x + bp_[0]; cB1 = uii.y + bp_[1]; cB2 = uii.z + bp_[2];
            mB0 = -2.f*cB0; mB1 = -2.f*cB1; mB2 = -2.f*cB2;
            cwB = fmaf(cB0,cB0, fmaf(cB1,cB1, cB2*cB2));
            const float* ap = g_a + ((size_t)(n*H_ + h)*L_ + iB)*3;
            float a0=ap[0], a1=ap[1], a2=ap[2];
            const float inv = 1.0f/(sqrtf(a0*a0+a1*a1+a2*a2) + EPS_);
            aB0=a0*inv; aB1=a1*inv; aB2=a2*inv;
            caB = fmaf(cB0,aB0, fmaf(cB1,aB1, cB2*aB2));
        }

        const float4* uAp = g_u + (size_t)(n*L_ + iA)*L_;
        const float4* uBp = g_u + (size_t)(n*L_ + iB)*L_;
        const float* stA_p = g_st + ((size_t)(n*H_ + h)*L_ + iA)*L_;
        const float* stB_p = g_st + ((size_t)(n*H_ + h)*L_ + iB)*L_;

        float sA=0.f, puA0=0.f, puA1=0.f, puA2=0.f, pthA=0.f;
        float sB=0.f, puB0=0.f, puB1=0.f, puB2=0.f, pthB=0.f;
        float avA[16], avB[16];
        #pragma unroll
        for (int d = 0; d < 16; d++) { avA[d]=0.f; avB[d]=0.f; }

        #pragma unroll 2
        for (int it = 0; it < 16; it++) {
            const int j = it*32 + lane;
            const float4 uA = __ldg(uAp + j);
            const float4 uB = __ldg(uBp + j);
            const float stA = __ldg(stA_p + j);
            const float stB = __ldg(stB_p + j);

            // row A
            float rrA = fmaf(mA0,uA.x, fmaf(mA1,uA.y, fmaf(mA2,uA.z, uA.w + cwA)));
            rrA = fmaxf(rrA, 1e-24f);
            const float irA = rsqrt_fast(rrA);
            const float rsA = rrA * irA;
            const float rdaA = fmaf(aA0,uA.x, fmaf(aA1,uA.y, fmaf(aA2,uA.z, -caA)));
            const float thA = acos_fast(rdaA * irA);
            float argA = fmaf(-al, rsA, fmaf(-be, thA, stA));
            if (j == iA) argA = -150.f;
            const float pA = ex2_fast(argA);

            // row B
            float rrB = fmaf(mB0,uB.x, fmaf(mB1,uB.y, fmaf(mB2,uB.z, uB.w + cwB)));
            rrB = fmaxf(rrB, 1e-24f);
            const float irB = rsqrt_fast(rrB);
            const float rsB = rrB * irB;
            const float rdaB = fmaf(aB0,uB.x, fmaf(aB1,uB.y, fmaf(aB2,uB.z, -caB)));
            const float thB = acos_fast(rdaB * irB);
            float argB = fmaf(-al, rsB, fmaf(-be, thB, stB));
            if (j == iB) argB = -150.f;
            const float pB = ex2_fast(argB);

            sA += pA; sB += pB;
            puA0=fmaf(pA,uA.x,puA0); puA1=fmaf(pA,uA.y,puA1); puA2=fmaf(pA,uA.z,puA2); pthA=fmaf(pA,thA,pthA);
            puB0=fmaf(pB,uB.x,puB0); puB1=fmaf(pB,uB.y,puB1); puB2=fmaf(pB,uB.z,puB2); pthB=fmaf(pB,thB,pthB);

            const float4* vj = (const float4*)(vs + j*KPAD);
            const float4 v0 = vj[0], v1 = vj[1], v2 = vj[2], v3 = vj[3];
            avA[0]=fmaf(pA,v0.x,avA[0]); avA[1]=fmaf(pA,v0.y,avA[1]); avA[2]=fmaf(pA,v0.z,avA[2]); avA[3]=fmaf(pA,v0.w,avA[3]);
            avA[4]=fmaf(pA,v1.x,avA[4]); avA[5]=fmaf(pA,v1.y,avA[5]); avA[6]=fmaf(pA,v1.z,avA[6]); avA[7]=fmaf(pA,v1.w,avA[7]);
            avA[8]=fmaf(pA,v2.x,avA[8]); avA[9]=fmaf(pA,v2.y,avA[9]); avA[10]=fmaf(pA,v2.z,avA[10]); avA[11]=fmaf(pA,v2.w,avA[11]);
            avA[12]=fmaf(pA,v3.x,avA[12]); avA[13]=fmaf(pA,v3.y,avA[13]); avA[14]=fmaf(pA,v3.z,avA[14]); avA[15]=fmaf(pA,v3.w,avA[15]);
            avB[0]=fmaf(pB,v0.x,avB[0]); avB[1]=fmaf(pB,v0.y,avB[1]); avB[2]=fmaf(pB,v0.z,avB[2]); avB[3]=fmaf(pB,v0.w,avB[3]);
            avB[4]=fmaf(pB,v1.x,avB[4]); avB[5]=fmaf(pB,v1.y,avB[5]); avB[6]=fmaf(pB,v1.z,avB[6]); avB[7]=fmaf(pB,v1.w,avB[7]);
            avB[8]=fmaf(pB,v2.x,avB[8]); avB[9]=fmaf(pB,v2.y,avB[9]); avB[10]=fmaf(pB,v2.z,avB[10]); avB[11]=fmaf(pB,v2.w,avB[11]);
            avB[12]=fmaf(pB,v3.x,avB[12]); avB[13]=fmaf(pB,v3.y,avB[13]); avB[14]=fmaf(pB,v3.z,avB[14]); avB[15]=fmaf(pB,v3.w,avB[15]);
        }

        float* ccA = g_cc + (size_t)(n*L_ + iA)*CH_;
        float* ccB = g_cc + (size_t)(n*L_ + iB)*CH_;
        attn_reduce_store(avA, sA, puA0, puA1, puA2, pthA, lane, ccA, h, cA0, cA1, cA2);
        attn_reduce_store(avB, sB, puB0, puB1, puB2, pthB, lane, ccB, h, cB0, cB1, cB2);
    }
}

// ================= kernel C: output projection =================
__global__ void out_kernel(const float* __restrict__ Wp, const float* __restrict__ bp,
                           float* __restrict__ out)
{
    __shared__ __align__(16) float cs[8*CH_];
    const int tid = threadIdx.x;
    const int r0 = blockIdx.x * 8;

    for (int idx = tid; idx < 8*CH_; idx += 128)
        cs[idx] = g_cc[(size_t)r0*CH_ + idx];
    __syncthreads();

    float acc[8];
    #pragma unroll
    for (int r = 0; r < 8; r++) acc[r] = 0.f;

    const float4* w4 = (const float4*)(Wp + (size_t)tid*CH_);
    #pragma unroll 2
    for (int k4 = 0; k4 < CH_/4; k4++) {
        const float4 w = w4[k4];
        #pragma unroll
        for (int r = 0; r < 8; r++) {
            const float4 cv = ((const float4*)(cs + r*CH_))[k4];
            acc[r] += cv.x*w.x + cv.y*w.y + cv.z*w.z + cv.w*w.w;
        }
    }
    const float bbv = bp[tid];
    #pragma unroll
    for (int r = 0; r < 8; r++)
        out[(size_t)(r0 + r)*HID_ + tid] = acc[r] + bbv;
}

// ---------------- launch ----------------
extern "C" void kernel_launch(void* const* d_in, const int* in_sizes, int n_in,
                              void* d_out, int out_size)
{
    const float* x     = (const float*)d_in[0];
    const float* R     = (const float*)d_in[1];
    const float* t     = (const float*)d_in[2];
    const float* Wq    = (const float*)d_in[4];
    const float* Wk    = (const float*)d_in[5];
    const float* Wv    = (const float*)d_in[6];
    const float* bv    = (const float*)d_in[7];
    const float* Wa    = (const float*)d_in[8];
    const float* ba    = (const float*)d_in[9];
    const float* Wb    = (const float*)d_in[10];
    const float* bb    = (const float*)d_in[11];
    const float* Wp    = (const float*)d_in[12];
    const float* bp    = (const float*)d_in[13];
    const float* alpha = (const float*)d_in[14];
    const float* beta  = (const float*)d_in[15];

    u_kernel<<<dim3(64, N_), 256>>>(R, t);
    proj_kernel<<<dim3(16, 21), 256>>>(x, Wq, Wk, Wv, bv, Wa, ba, Wb, bb);
    st_kernel<<<dim3(8, 8, N_*H_), 256>>>();
    attn_kernel<<<dim3(8, H_, N_), 256>>>(alpha, beta);
    out_kernel<<<dim3(128), 128>>>(Wp, bp, (float*)d_out);
}

// round 10
// speedup vs baseline: 1.1469x; 1.1469x over previous
#include <cuda_runtime.h>
#include <math.h>

#define N_    2
#define L_    512
#define H_    24
#define QK_   16
#define V_    16
#define HID_  128
#define CH_   504
#define EPS_  1e-6f
#define KPAD  20

// ---------------- scratch ----------------
__device__ float  g_q [N_*L_*H_*QK_];   // [n*L+i][h*16+d]
__device__ float  g_kT[N_*H_*QK_*L_];   // [n][h][d][j]
__device__ float  g_vT[N_*H_*V_ *L_];   // [n][h][d][j]
__device__ float  g_a [N_*H_*L_*3];
__device__ float  g_b [N_*H_*L_*3];
__device__ float  g_cc[N_*L_*CH_];
__device__ float  g_uw[(size_t)N_*L_*L_];      // |R_i^T t_j|^2   2MB
__device__ float  g_st[(size_t)N_*H_*L_*L_];   // c1*q.k + bias  50MB

__device__ __forceinline__ float rsqrt_fast(float x) {
    float r; asm("rsqrt.approx.f32 %0,%1;" : "=f"(r) : "f"(x)); return r;
}
__device__ __forceinline__ float ex2_fast(float x) {
    float r; asm("ex2.approx.f32 %0,%1;" : "=f"(r) : "f"(x)); return r;
}
// fast acos with built-in clamp: A&S 4.4.45, |err| <= 6.8e-5 (budget 1e-3)
__device__ __forceinline__ float acos_fast(float x) {
    float ax = fminf(fabsf(x), 1.0f);
    float s; asm("sqrt.approx.f32 %0,%1;" : "=f"(s) : "f"(1.0f - ax));
    float p = fmaf(ax, -0.0187293f, 0.0742610f);
    p = fmaf(ax, p, -0.2121144f);
    p = fmaf(ax, p, 1.5707288f);
    float r = s * p;
    return x < 0.f ? 3.14159265359f - r : r;
}

// ================= kernel A: fused projections (proven ~22us) =================
#define PJS 68

__global__ void __launch_bounds__(256) proj_kernel(
    const float* __restrict__ x,
    const float* __restrict__ Wq, const float* __restrict__ Wk,
    const float* __restrict__ Wv, const float* __restrict__ bv,
    const float* __restrict__ Wa, const float* __restrict__ ba,
    const float* __restrict__ Wb, const float* __restrict__ bb)
{
    __shared__ float xs[32*PJS];
    __shared__ float ws[32*PJS];

    const int tid = threadIdx.x;
    const int rt  = blockIdx.x;
    const int ct  = blockIdx.y;

    const int tx = tid & 15;
    const int ty = tid >> 4;

    float acc[4][4];
    #pragma unroll
    for (int r = 0; r < 4; r++)
        #pragma unroll
        for (int c = 0; c < 4; c++) acc[r][c] = 0.f;

    #pragma unroll 1
    for (int chunk = 0; chunk < 4; chunk++) {
        __syncthreads();
        #pragma unroll
        for (int it = 0; it < 2; it++) {
            const int idx = it*256 + tid;
            const int kq = idx & 7;
            const int m  = idx >> 3;
            const float4 v = *(const float4*)(x + (size_t)(rt*64 + m)*HID_ + chunk*32 + kq*4);
            xs[(kq*4+0)*PJS + m] = v.x;
            xs[(kq*4+1)*PJS + m] = v.y;
            xs[(kq*4+2)*PJS + m] = v.z;
            xs[(kq*4+3)*PJS + m] = v.w;
        }
        #pragma unroll
        for (int it = 0; it < 2; it++) {
            const int idx = it*256 + tid;
            const int kq = idx & 7;
            const int cl = idx >> 3;
            const int c  = min(ct*64 + cl, 1295);
            const float* wrow;
            if      (c <  384) wrow = Wq + (size_t)c*HID_;
            else if (c <  768) wrow = Wk + (size_t)(c- 384)*HID_;
            else if (c < 1152) wrow = Wv + (size_t)(c- 768)*HID_;
            else if (c < 1224) wrow = Wa + (size_t)(c-1152)*HID_;
            else               wrow = Wb + (size_t)(c-1224)*HID_;
            const float4 v = *(const float4*)(wrow + chunk*32 + kq*4);
            ws[(kq*4+0)*PJS + cl] = v.x;
            ws[(kq*4+1)*PJS + cl] = v.y;
            ws[(kq*4+2)*PJS + cl] = v.z;
            ws[(kq*4+3)*PJS + cl] = v.w;
        }
        __syncthreads();

        #pragma unroll
        for (int k = 0; k < 32; k++) {
            const float4 xv = *(const float4*)(xs + k*PJS + tx*4);
            const float4 wv = *(const float4*)(ws + k*PJS + ty*4);
            const float xa[4] = {xv.x, xv.y, xv.z, xv.w};
            const float wa[4] = {wv.x, wv.y, wv.z, wv.w};
            #pragma unroll
            for (int r = 0; r < 4; r++)
                #pragma unroll
                for (int c = 0; c < 4; c++)
                    acc[r][c] = fmaf(xa[r], wa[c], acc[r][c]);
        }
    }

    #pragma unroll
    for (int r = 0; r < 4; r++) {
        const int gi = rt*64 + tx*4 + r;
        const int n = gi >> 9, i = gi & 511;
        #pragma unroll
        for (int cv = 0; cv < 4; cv++) {
            const int c = ct*64 + ty*4 + cv;
            if (c >= 1296) continue;
            float val = acc[r][cv];
            if (c < 384) {
                g_q[(size_t)gi*384 + c] = val;
            } else if (c < 768) {
                int cc = c - 384; int h = cc >> 4, d = cc & 15;
                g_kT[((size_t)(n*H_ + h)*QK_ + d)*L_ + i] = val;
            } else if (c < 1152) {
                int cc = c - 768; int h = cc >> 4, d = cc & 15;
                g_vT[((size_t)(n*H_ + h)*V_ + d)*L_ + i] = val + bv[cc];
            } else if (c < 1224) {
                int cc = c - 1152; int h = cc/3, xx = cc - h*3;
                g_a[((size_t)(n*H_ + h)*L_ + i)*3 + xx] = val + ba[cc];
            } else {
                int cc = c - 1224; int h = cc/3, xx = cc - h*3;
                g_b[((size_t)(n*H_ + h)*L_ + i)*3 + xx] = val + bb[cc];
            }
        }
    }
}

// ================= kernel U: uw[n][i][j] = |R_i^T t_j|^2 =================
__global__ void __launch_bounds__(256) u_kernel(
    const float* __restrict__ Rm, const float* __restrict__ t)
{
    __shared__ float4 ts4[L_];
    const int tid = threadIdx.x;
    const int n = blockIdx.y;
    const int i = blockIdx.x*8 + (tid >> 5);
    const int lane = tid & 31;

    for (int j = tid; j < L_; j += 256) {
        const float* tp = t + (size_t)(n*L_ + j)*3;
        ts4[j] = make_float4(tp[0], tp[1], tp[2], 0.f);
    }
    __syncthreads();

    const float* Rp = Rm + (size_t)(n*L_ + i)*9;
    const float R00=Rp[0],R01=Rp[1],R02=Rp[2],
                R10=Rp[3],R11=Rp[4],R12=Rp[5],
                R20=Rp[6],R21=Rp[7],R22=Rp[8];

    float* up = g_uw + (size_t)(n*L_ + i)*L_;
    #pragma unroll 2
    for (int it = 0; it < 16; it++) {
        const int j = it*32 + lane;
        const float4 tj = ts4[j];
        const float ux = R00*tj.x + R10*tj.y + R20*tj.z;
        const float uy = R01*tj.x + R11*tj.y + R21*tj.z;
        const float uz = R02*tj.x + R12*tj.y + R22*tj.z;
        up[j] = fmaf(ux,ux, fmaf(uy,uy, uz*uz));
    }
}

// ================= kernel S: st = c1*(q.k) + bias  (batched GEMM) =================
__global__ void __launch_bounds__(256) st_kernel()
{
    __shared__ float qs[16*68];   // [d][i_local]
    __shared__ float ksm[16*64];  // [d][j_local]

    const int tid = threadIdx.x;
    const int i0 = blockIdx.x * 64;
    const int j0 = blockIdx.y * 64;
    const int nh = blockIdx.z;
    const int n = nh / H_, h = nh - n*H_;

    {
        const int il = tid >> 2, dq = tid & 3;
        const float4 v = *(const float4*)(g_q + (size_t)(n*L_ + i0 + il)*384 + h*16 + dq*4);
        qs[(dq*4+0)*68 + il] = v.x;
        qs[(dq*4+1)*68 + il] = v.y;
        qs[(dq*4+2)*68 + il] = v.z;
        qs[(dq*4+3)*68 + il] = v.w;
    }
    {
        const int dk = tid >> 4, j4 = tid & 15;
        const float4 v = *(const float4*)(g_kT + ((size_t)nh*16 + dk)*L_ + j0 + j4*4);
        *(float4*)(ksm + dk*64 + j4*4) = v;
    }
    __syncthreads();

    const int tx = tid & 15;
    const int ty = tid >> 4;

    float acc[4][4];
    #pragma unroll
    for (int r = 0; r < 4; r++)
        #pragma unroll
        for (int c = 0; c < 4; c++) acc[r][c] = 0.f;

    #pragma unroll
    for (int d = 0; d < 16; d++) {
        const float4 qv = *(const float4*)(qs + d*68 + ty*4);
        const float4 kv = *(const float4*)(ksm + d*64 + tx*4);
        const float qa[4] = {qv.x, qv.y, qv.z, qv.w};
        const float ka[4] = {kv.x, kv.y, kv.z, kv.w};
        #pragma unroll
        for (int r = 0; r < 4; r++)
            #pragma unroll
            for (int c = 0; c < 4; c++)
                acc[r][c] = fmaf(qa[r], ka[c], acc[r][c]);
    }

    const float C1 = 0.70710678118f * 0.25f * 1.44269504089f;
    const float BIAS = -4.0f * 1.44269504089f;
    #pragma unroll
    for (int r = 0; r < 4; r++) {
        const int i = i0 + ty*4 + r;
        float4 o;
        o.x = fmaf(C1, acc[r][0], BIAS);
        o.y = fmaf(C1, acc[r][1], BIAS);
        o.z = fmaf(C1, acc[r][2], BIAS);
        o.w = fmaf(C1, acc[r][3], BIAS);
        *(float4*)(g_st + ((size_t)nh*L_ + i)*L_ + j0 + tx*4) = o;
    }
}

// ================= kernel B: ray attention (t-based, 1 row/warp) =================
// rr  = uw - 2 t.(R c) + |c|^2
// r.a'= t.(R a') - c.a'
// sum(p r) = R^T (sum p t) - s c  (fixed after loop)
#define ATTN_SMEM ((L_*KPAD + 4*L_)*4)   // vs + ts4 = 49152 B

__global__ void __launch_bounds__(256, 3) attn_kernel(
    const float* __restrict__ Rm,
    const float* __restrict__ alpha, const float* __restrict__ beta)
{
    extern __shared__ float sm[];
    float*  vs  = sm;                     // [512][20]
    float4* ts4 = (float4*)(sm + L_*KPAD);

    const int tid = threadIdx.x;
    const int n = blockIdx.z, h = blockIdx.y;
    const int i0 = blockIdx.x * 64;

    const float* vb = g_vT + (size_t)(n*H_ + h)*V_*L_;
    for (int idx = tid; idx < QK_*L_; idx += 256) {
        int d = idx >> 9, j = idx & 511;
        vs[j*KPAD + d] = vb[idx];
    }
    // t for this n: reconstruct from uw? no — need raw t; pull through g_b? use Rm? t is an input; pass t via ts fill from g_uw? No: t is available as const arg of u_kernel only. Load from global t through Rm arg? We pass t too.
    __syncthreads();

    const float LOG2E = 1.44269504089f;
    const float al = log1pf(expf(alpha[h])) * 0.70710678118f * LOG2E;
    const float be = log1pf(expf(beta[h]))  * 0.70710678118f * LOG2E;
    const int warp = tid >> 5, lane = tid & 31;

    #pragma unroll 1
    for (int pass = 0; pass < 8; pass++) {
        const int i = i0 + warp*8 + pass;

        // ---- per-row prologue ----
        float w1x, w1y, w1z, w2x, w2y, w2z, cw, ca, c0, c1, c2;
        {
            const float* Rp = Rm + (size_t)(n*L_ + i)*9;
            const float R00=Rp[0],R01=Rp[1],R02=Rp[2],
                        R10=Rp[3],R11=Rp[4],R12=Rp[5],
                        R20=Rp[6],R21=Rp[7],R22=Rp[8];
            const float4 ti = ts4[i];
            const float* bp_ = g_b + ((size_t)(n*H_ + h)*L_ + i)*3;
            // c = R^T t_i + b
            c0 = R00*ti.x + R10*ti.y + R20*ti.z + bp_[0];
            c1 = R01*ti.x + R11*ti.y + R21*ti.z + bp_[1];
            c2 = R02*ti.x + R12*ti.y + R22*ti.z + bp_[2];
            cw = fmaf(c0,c0, fmaf(c1,c1, c2*c2));
            const float* ap = g_a + ((size_t)(n*H_ + h)*L_ + i)*3;
            float a0=ap[0], a1=ap[1], a2=ap[2];
            const float inv = 1.0f/(sqrtf(a0*a0+a1*a1+a2*a2) + EPS_);
            a0 *= inv; a1 *= inv; a2 *= inv;
            ca = fmaf(c0,a0, fmaf(c1,a1, c2*a2));
            // w1 = -2 R c (row-major R: (Rc)_d = R[d][.] . c)
            w1x = -2.f*(R00*c0 + R01*c1 + R02*c2);
            w1y = -2.f*(R10*c0 + R11*c1 + R12*c2);
            w1z = -2.f*(R20*c0 + R21*c1 + R22*c2);
            // w2 = R a'
            w2x = R00*a0 + R01*a1 + R02*a2;
            w2y = R10*a0 + R11*a1 + R12*a2;
            w2z = R20*a0 + R21*a1 + R22*a2;
        }

        const float* uwp = g_uw + (size_t)(n*L_ + i)*L_;
        const float* stp = g_st + ((size_t)(n*H_ + h)*L_ + i)*L_;

        float s=0.f, pt0=0.f, pt1=0.f, pt2=0.f, pth=0.f;
        float av[16];
        #pragma unroll
        for (int d = 0; d < 16; d++) av[d] = 0.f;

        #pragma unroll 2
        for (int it = 0; it < 16; it++) {
            const int j = it*32 + lane;
            const float uw = __ldg(uwp + j);
            const float st = __ldg(stp + j);
            const float4 tj = ts4[j];

            float rr = fmaf(w1x,tj.x, fmaf(w1y,tj.y, fmaf(w1z,tj.z, uw + cw)));
            rr = fmaxf(rr, 1e-24f);
            const float ir = rsqrt_fast(rr);
            const float rs = rr * ir;
            const float rda = fmaf(w2x,tj.x, fmaf(w2y,tj.y, fmaf(w2z,tj.z, -ca)));
            const float th = acos_fast(rda * ir);
            float arg = fmaf(-al, rs, fmaf(-be, th, st));
            if (j == i) arg = -150.f;
            const float p = ex2_fast(arg);

            s += p;
            pt0 = fmaf(p, tj.x, pt0);
            pt1 = fmaf(p, tj.y, pt1);
            pt2 = fmaf(p, tj.z, pt2);
            pth = fmaf(p, th,  pth);

            const float4* vj = (const float4*)(vs + j*KPAD);
            const float4 v0 = vj[0], v1 = vj[1], v2 = vj[2], v3 = vj[3];
            av[0] =fmaf(p,v0.x,av[0]);  av[1] =fmaf(p,v0.y,av[1]);  av[2] =fmaf(p,v0.z,av[2]);  av[3] =fmaf(p,v0.w,av[3]);
            av[4] =fmaf(p,v1.x,av[4]);  av[5] =fmaf(p,v1.y,av[5]);  av[6] =fmaf(p,v1.z,av[6]);  av[7] =fmaf(p,v1.w,av[7]);
            av[8] =fmaf(p,v2.x,av[8]);  av[9] =fmaf(p,v2.y,av[9]);  av[10]=fmaf(p,v2.z,av[10]); av[11]=fmaf(p,v2.w,av[11]);
            av[12]=fmaf(p,v3.x,av[12]); av[13]=fmaf(p,v3.y,av[13]); av[14]=fmaf(p,v3.z,av[14]); av[15]=fmaf(p,v3.w,av[15]);
        }

        // ---- reduction ----
        #pragma unroll
        for (int k = 0; k < 4; k++) {
            const int half = 8 >> k;
            const bool up = (lane >> k) & 1;
            #pragma unroll
            for (int t2 = 0; t2 < half; t2++) {
                float send = up ? av[t2] : av[t2 + half];
                float recv = __shfl_xor_sync(0xffffffffu, send, 1 << k);
                av[t2] = (up ? av[t2 + half] : av[t2]) + recv;
            }
        }
        av[0] += __shfl_xor_sync(0xffffffffu, av[0], 16);

        #pragma unroll
        for (int off = 16; off > 0; off >>= 1) {
            s   += __shfl_xor_sync(0xffffffffu, s,   off);
            pt0 += __shfl_xor_sync(0xffffffffu, pt0, off);
            pt1 += __shfl_xor_sync(0xffffffffu, pt1, off);
            pt2 += __shfl_xor_sync(0xffffffffu, pt2, off);
            pth += __shfl_xor_sync(0xffffffffu, pth, off);
        }
        const float inv = 1.0f / s;
        float* cc = g_cc + (size_t)(n*L_ + i)*CH_;
        if (lane < 16) {
            const int d = (int)(__brev((unsigned)lane) >> 28);
            cc[h*16 + d] = av[0] * inv;
        }
        if (lane == 0) {
            const float* Rp = Rm + (size_t)(n*L_ + i)*9;
            // r_aggr = R^T (sum p t)/s - c
            const float ra0 = (Rp[0]*pt0 + Rp[3]*pt1 + Rp[6]*pt2)*inv - c0;
            const float ra1 = (Rp[1]*pt0 + Rp[4]*pt1 + Rp[7]*pt2)*inv - c1;
            const float ra2 = (Rp[2]*pt0 + Rp[5]*pt1 + Rp[8]*pt2)*inv - c2;
            cc[384 + h*3 + 0] = ra0;
            cc[384 + h*3 + 1] = ra1;
            cc[384 + h*3 + 2] = ra2;
            cc[456 + h] = sqrtf(ra0*ra0 + ra1*ra1 + ra2*ra2);
            cc[480 + h] = pth*inv;
        }
    }
}

// fill ts4 for attn (t must be in smem): tiny helper fused into attn via arg
__global__ void __launch_bounds__(256) noop_kernel() {}

// ================= kernel C: output projection =================
__global__ void out_kernel(const float* __restrict__ Wp, const float* __restrict__ bp,
                           float* __restrict__ out)
{
    __shared__ __align__(16) float cs[8*CH_];
    const int tid = threadIdx.x;
    const int r0 = blockIdx.x * 8;

    for (int idx = tid; idx < 8*CH_; idx += 128)
        cs[idx] = g_cc[(size_t)r0*CH_ + idx];
    __syncthreads();

    float acc[8];
    #pragma unroll
    for (int r = 0; r < 8; r++) acc[r] = 0.f;

    const float4* w4 = (const float4*)(Wp + (size_t)tid*CH_);
    #pragma unroll 2
    for (int k4 = 0; k4 < CH_/4; k4++) {
        const float4 w = w4[k4];
        #pragma unroll
        for (int r = 0; r < 8; r++) {
            const float4 cv = ((const float4*)(cs + r*CH_))[k4];
            acc[r] += cv.x*w.x + cv.y*w.y + cv.z*w.z + cv.w*w.w;
        }
    }
    const float bbv = bp[tid];
    #pragma unroll
    for (int r = 0; r < 8; r++)
        out[(size_t)(r0 + r)*HID_ + tid] = acc[r] + bbv;
}

// attn needs t in smem: we add the fill inside attn via an extra kernel arg.
// (re-declare attn with t pointer; the definition above uses ts4 filled here)
__global__ void __launch_bounds__(256) ts_fill_check() {}

extern "C" void kernel_launch(void* const* d_in, const int* in_sizes, int n_in,
                              void* d_out, int out_size);

// ---- real attn wrapper: fill ts4 then run (single kernel, t passed in) ----
// To keep one definition, we redefine attn launch to pass t and fill ts4 at top.
// (The fill loop was omitted above intentionally; add it via this shim.)
__global__ void __launch_bounds__(256, 3) attn_kernel_t(
    const float* __restrict__ Rm, const float* __restrict__ t,
    const float* __restrict__ alpha, const float* __restrict__ beta)
{
    extern __shared__ float sm[];
    float*  vs  = sm;
    float4* ts4 = (float4*)(sm + L_*KPAD);

    const int tid = threadIdx.x;
    const int n = blockIdx.z, h = blockIdx.y;
    const int i0 = blockIdx.x * 64;

    const float* vb = g_vT + (size_t)(n*H_ + h)*V_*L_;
    for (int idx = tid; idx < QK_*L_; idx += 256) {
        int d = idx >> 9, j = idx & 511;
        vs[j*KPAD + d] = vb[idx];
    }
    for (int j = tid; j < L_; j += 256) {
        const float* tp = t + (size_t)(n*L_ + j)*3;
        ts4[j] = make_float4(tp[0], tp[1], tp[2], 0.f);
    }
    __syncthreads();

    const float LOG2E = 1.44269504089f;
    const float al = log1pf(expf(alpha[h])) * 0.70710678118f * LOG2E;
    const float be = log1pf(expf(beta[h]))  * 0.70710678118f * LOG2E;
    const int warp = tid >> 5, lane = tid & 31;

    #pragma unroll 1
    for (int pass = 0; pass < 8; pass++) {
        const int i = i0 + warp*8 + pass;

        float w1x, w1y, w1z, w2x, w2y, w2z, cw, ca, c0, c1, c2;
        {
            const float* Rp = Rm + (size_t)(n*L_ + i)*9;
            const float R00=Rp[0],R01=Rp[1],R02=Rp[2],
                        R10=Rp[3],R11=Rp[4],R12=Rp[5],
                        R20=Rp[6],R21=Rp[7],R22=Rp[8];
            const float4 ti = ts4[i];
            const float* bp_ = g_b + ((size_t)(n*H_ + h)*L_ + i)*3;
            c0 = R00*ti.x + R10*ti.y + R20*ti.z + bp_[0];
            c1 = R01*ti.x + R11*ti.y + R21*ti.z + bp_[1];
            c2 = R02*ti.x + R12*ti.y + R22*ti.z + bp_[2];
            cw = fmaf(c0,c0, fmaf(c1,c1, c2*c2));
            const float* ap = g_a + ((size_t)(n*H_ + h)*L_ + i)*3;
            float a0=ap[0], a1=ap[1], a2=ap[2];
            const float inv = 1.0f/(sqrtf(a0*a0+a1*a1+a2*a2) + EPS_);
            a0 *= inv; a1 *= inv; a2 *= inv;
            ca = fmaf(c0,a0, fmaf(c1,a1, c2*a2));
            w1x = -2.f*(R00*c0 + R01*c1 + R02*c2);
            w1y = -2.f*(R10*c0 + R11*c1 + R12*c2);
            w1z = -2.f*(R20*c0 + R21*c1 + R22*c2);
            w2x = R00*a0 + R01*a1 + R02*a2;
            w2y = R10*a0 + R11*a1 + R12*a2;
            w2z = R20*a0 + R21*a1 + R22*a2;
        }

        const float* uwp = g_uw + (size_t)(n*L_ + i)*L_;
        const float* stp = g_st + ((size_t)(n*H_ + h)*L_ + i)*L_;

        float s=0.f, pt0=0.f, pt1=0.f, pt2=0.f, pth=0.f;
        float av[16];
        #pragma unroll
        for (int d = 0; d < 16; d++) av[d] = 0.f;

        #pragma unroll 2
        for (int it = 0; it < 16; it++) {
            const int j = it*32 + lane;
            const float uw = __ldg(uwp + j);
            const float st = __ldg(stp + j);
            const float4 tj = ts4[j];

            float rr = fmaf(w1x,tj.x, fmaf(w1y,tj.y, fmaf(w1z,tj.z, uw + cw)));
            rr = fmaxf(rr, 1e-24f);
            const float ir = rsqrt_fast(rr);
            const float rs = rr * ir;
            const float rda = fmaf(w2x,tj.x, fmaf(w2y,tj.y, fmaf(w2z,tj.z, -ca)));
            const float th = acos_fast(rda * ir);
            float arg = fmaf(-al, rs, fmaf(-be, th, st));
            if (j == i) arg = -150.f;
            const float p = ex2_fast(arg);

            s += p;
            pt0 = fmaf(p, tj.x, pt0);
            pt1 = fmaf(p, tj.y, pt1);
            pt2 = fmaf(p, tj.z, pt2);
            pth = fmaf(p, th,  pth);

            const float4* vj = (const float4*)(vs + j*KPAD);
            const float4 v0 = vj[0], v1 = vj[1], v2 = vj[2], v3 = vj[3];
            av[0] =fmaf(p,v0.x,av[0]);  av[1] =fmaf(p,v0.y,av[1]);  av[2] =fmaf(p,v0.z,av[2]);  av[3] =fmaf(p,v0.w,av[3]);
            av[4] =fmaf(p,v1.x,av[4]);  av[5] =fmaf(p,v1.y,av[5]);  av[6] =fmaf(p,v1.z,av[6]);  av[7] =fmaf(p,v1.w,av[7]);
            av[8] =fmaf(p,v2.x,av[8]);  av[9] =fmaf(p,v2.y,av[9]);  av[10]=fmaf(p,v2.z,av[10]); av[11]=fmaf(p,v2.w,av[11]);
            av[12]=fmaf(p,v3.x,av[12]); av[13]=fmaf(p,v3.y,av[13]); av[14]=fmaf(p,v3.z,av[14]); av[15]=fmaf(p,v3.w,av[15]);
        }

        #pragma unroll
        for (int k = 0; k < 4; k++) {
            const int half = 8 >> k;
            const bool up = (lane >> k) & 1;
            #pragma unroll
            for (int t2 = 0; t2 < half; t2++) {
                float send = up ? av[t2] : av[t2 + half];
                float recv = __shfl_xor_sync(0xffffffffu, send, 1 << k);
                av[t2] = (up ? av[t2 + half] : av[t2]) + recv;
            }
        }
        av[0] += __shfl_xor_sync(0xffffffffu, av[0], 16);

        #pragma unroll
        for (int off = 16; off > 0; off >>= 1) {
            s   += __shfl_xor_sync(0xffffffffu, s,   off);
            pt0 += __shfl_xor_sync(0xffffffffu, pt0, off);
            pt1 += __shfl_xor_sync(0xffffffffu, pt1, off);
            pt2 += __shfl_xor_sync(0xffffffffu, pt2, off);
            pth += __shfl_xor_sync(0xffffffffu, pth, off);
        }
        const float inv = 1.0f / s;
        float* cc = g_cc + (size_t)(n*L_ + i)*CH_;
        if (lane < 16) {
            const int d = (int)(__brev((unsigned)lane) >> 28);
            cc[h*16 + d] = av[0] * inv;
        }
        if (lane == 0) {
            const float* Rp = Rm + (size_t)(n*L_ + i)*9;
            const float ra0 = (Rp[0]*pt0 + Rp[3]*pt1 + Rp[6]*pt2)*inv - c0;
            const float ra1 = (Rp[1]*pt0 + Rp[4]*pt1 + Rp[7]*pt2)*inv - c1;
            const float ra2 = (Rp[2]*pt0 + Rp[5]*pt1 + Rp[8]*pt2)*inv - c2;
            cc[384 + h*3 + 0] = ra0;
            cc[384 + h*3 + 1] = ra1;
            cc[384 + h*3 + 2] = ra2;
            cc[456 + h] = sqrtf(ra0*ra0 + ra1*ra1 + ra2*ra2);
            cc[480 + h] = pth*inv;
        }
    }
}

// ---------------- launch ----------------
extern "C" void kernel_launch(void* const* d_in, const int* in_sizes, int n_in,
                              void* d_out, int out_size)
{
    const float* x     = (const float*)d_in[0];
    const float* R     = (const float*)d_in[1];
    const float* t     = (const float*)d_in[2];
    const float* Wq    = (const float*)d_in[4];
    const float* Wk    = (const float*)d_in[5];
    const float* Wv    = (const float*)d_in[6];
    const float* bv    = (const float*)d_in[7];
    const float* Wa    = (const float*)d_in[8];
    const float* ba    = (const float*)d_in[9];
    const float* Wb    = (const float*)d_in[10];
    const float* bb    = (const float*)d_in[11];
    const float* Wp    = (const float*)d_in[12];
    const float* bp    = (const float*)d_in[13];
    const float* alpha = (const float*)d_in[14];
    const float* beta  = (const float*)d_in[15];

    u_kernel<<<dim3(64, N_), 256>>>(R, t);
    proj_kernel<<<dim3(16, 21), 256>>>(x, Wq, Wk, Wv, bv, Wa, ba, Wb, bb);
    st_kernel<<<dim3(8, 8, N_*H_), 256>>>();
    cudaFuncSetAttribute(attn_kernel_t, cudaFuncAttributeMaxDynamicSharedMemorySize, ATTN_SMEM);
    attn_kernel_t<<<dim3(8, H_, N_), 256, ATTN_SMEM>>>(R, t, alpha, beta);
    out_kernel<<<dim3(128), 128>>>(Wp, bp, (float*)d_out);
}